// round 1
// baseline (speedup 1.0000x reference)
#include <cuda_runtime.h>
#include <cstdint>

#define M_DIM 4096
#define K_DIM 4096
#define B_DIM 4
#define N_DIM 2048
#define NNZ_PER_ROW 409

// Scratch for transposed activations: xT[B][K][N], 128 MiB.
__device__ float g_xT[(size_t)B_DIM * K_DIM * N_DIM];

// ---------------------------------------------------------------------------
// Kernel 1: transpose x [B, N, K] -> xT [B, K, N]
// ---------------------------------------------------------------------------
__global__ void transpose_kernel(const float* __restrict__ x) {
    __shared__ float tile[32][33];
    const int b  = blockIdx.z;
    const int k0 = blockIdx.x * 32;   // column block in x == row block in xT
    const int n0 = blockIdx.y * 32;   // row block in x == column block in xT

    const float* xb  = x    + (size_t)b * N_DIM * K_DIM;
    float*       xTb = g_xT + (size_t)b * K_DIM * N_DIM;

    #pragma unroll
    for (int i = threadIdx.y; i < 32; i += 8) {
        tile[i][threadIdx.x] = xb[(size_t)(n0 + i) * K_DIM + (k0 + threadIdx.x)];
    }
    __syncthreads();
    #pragma unroll
    for (int i = threadIdx.y; i < 32; i += 8) {
        xTb[(size_t)(k0 + i) * N_DIM + (n0 + threadIdx.x)] = tile[threadIdx.x][i];
    }
}

// ---------------------------------------------------------------------------
// Kernel 2: SpMM. One block per (n_chunk, m, b).
//   out[b][m][n] = sum_j vals[j] * xT[b][cols[j]][n]
// 128 threads * float4 = 512 n-values per block.
// ---------------------------------------------------------------------------
__global__ void __launch_bounds__(128) spmm_kernel(
    const float* __restrict__ values,
    const int*   __restrict__ row_offsets,
    const int*   __restrict__ col_indices,
    float*       __restrict__ out)
{
    __shared__ float sv[NNZ_PER_ROW];
    __shared__ int   sc[NNZ_PER_ROW];

    const int m = blockIdx.y;
    const int b = blockIdx.z;
    const int n = blockIdx.x * (128 * 4) + threadIdx.x * 4;

    const int start = row_offsets[m];
    const int end   = row_offsets[m + 1];
    const int cnt   = end - start;

    for (int j = threadIdx.x; j < cnt; j += 128) {
        sv[j] = values[start + j];
        sc[j] = col_indices[start + j];
    }
    __syncthreads();

    const float* xb = g_xT + (size_t)b * K_DIM * N_DIM;

    float4 acc = make_float4(0.f, 0.f, 0.f, 0.f);

    #pragma unroll 4
    for (int j = 0; j < cnt; ++j) {
        const float v = sv[j];
        const int   c = sc[j];
        const float4 xv = *reinterpret_cast<const float4*>(xb + (size_t)c * N_DIM + n);
        acc.x = fmaf(v, xv.x, acc.x);
        acc.y = fmaf(v, xv.y, acc.y);
        acc.z = fmaf(v, xv.z, acc.z);
        acc.w = fmaf(v, xv.w, acc.w);
    }

    float* op = out + ((size_t)b * M_DIM + m) * N_DIM + n;
    *reinterpret_cast<float4*>(op) = acc;
}

// ---------------------------------------------------------------------------
extern "C" void kernel_launch(void* const* d_in, const int* in_sizes, int n_in,
                              void* d_out, int out_size) {
    const float* x           = (const float*)d_in[0];  // [B, N, K]
    const float* values      = (const float*)d_in[1];  // [NNZ]
    const int*   row_offsets = (const int*)  d_in[2];  // [M+1]
    const int*   col_indices = (const int*)  d_in[3];  // [NNZ]
    float*       out         = (float*)d_out;          // [B, M, N]

    (void)in_sizes; (void)n_in; (void)out_size;

    // 1) transpose x -> g_xT
    dim3 tgrid(K_DIM / 32, N_DIM / 32, B_DIM);
    dim3 tblock(32, 8);
    transpose_kernel<<<tgrid, tblock>>>(x);

    // 2) SpMM
    dim3 sgrid(N_DIM / 512, M_DIM, B_DIM);
    spmm_kernel<<<sgrid, 128>>>(values, row_offsets, col_indices, out);
}

// round 3
// speedup vs baseline: 1.2796x; 1.2796x over previous
#include <cuda_runtime.h>
#include <cuda_fp16.h>
#include <cstdint>

#define M_DIM 4096
#define K_DIM 4096
#define B_DIM 4
#define N_DIM 2048
#define BN_DIM (B_DIM * N_DIM)      // 8192

// GEMM tiling
#define BM 128
#define BN 128
#define BK 32                        // fp16 elems per k-tile
#define NSTAGE 4
#define PADK 40                      // smem row pitch in halves (80 B) -> conflict-free frags
#define TILE_ROW_BYTES (PADK * 2)    // 80
#define TILE_BYTES (BM * TILE_ROW_BYTES)      // 10240 per operand tile
#define STAGE_BYTES (3 * TILE_BYTES)          // Ahi + Alo + B = 30720
#define SMEM_TOTAL (NSTAGE * STAGE_BYTES)     // 122880
#define NKT (K_DIM / BK)             // 128

// ---------------- scratch (device globals; no runtime allocation) ----------
__device__ __align__(1024) float  g_Wd [(size_t)M_DIM * K_DIM];
__device__ __align__(1024) __half g_Whi[(size_t)M_DIM * K_DIM];
__device__ __align__(1024) __half g_Wlo[(size_t)M_DIM * K_DIM];
__device__ __align__(1024) __half g_Xh [(size_t)BN_DIM * K_DIM];

// ---------------- helpers ---------------------------------------------------
__device__ __forceinline__ uint32_t smem_u32(const void* p) {
    uint32_t a;
    asm("{ .reg .u64 t; cvta.to.shared.u64 t, %1; cvt.u32.u64 %0, t; }" : "=r"(a) : "l"(p));
    return a;
}

#define CP16(dst_u32, src_ptr) \
    asm volatile("cp.async.cg.shared.global [%0], [%1], 16;" \
                 :: "r"(dst_u32), "l"(src_ptr) : "memory")
#define CP_COMMIT() asm volatile("cp.async.commit_group;" ::: "memory")
#define CP_WAIT(n)  asm volatile("cp.async.wait_group %0;" :: "n"(n) : "memory")

__device__ __forceinline__ void mma16816(float* d, const uint32_t* a, const uint32_t* b) {
    asm volatile(
        "mma.sync.aligned.m16n8k16.row.col.f32.f16.f16.f32 "
        "{%0,%1,%2,%3}, {%4,%5,%6,%7}, {%8,%9}, {%0,%1,%2,%3};"
        : "+f"(d[0]), "+f"(d[1]), "+f"(d[2]), "+f"(d[3])
        : "r"(a[0]), "r"(a[1]), "r"(a[2]), "r"(a[3]), "r"(b[0]), "r"(b[1]));
}

// ---------------- prep kernels ----------------------------------------------
__global__ void __launch_bounds__(256) zero_w_kernel() {
    size_t i = ((size_t)blockIdx.x * 256 + threadIdx.x) * 4;
    if (i < (size_t)M_DIM * K_DIM)
        *reinterpret_cast<float4*>(&g_Wd[i]) = make_float4(0.f, 0.f, 0.f, 0.f);
}

// Deterministic CSR scatter: columns are sorted per row; fold duplicate runs.
__global__ void __launch_bounds__(128) scatter_kernel(
    const float* __restrict__ values, const int* __restrict__ row_offsets,
    const int* __restrict__ cols) {
    const int m = blockIdx.x;
    const int s = row_offsets[m], e = row_offsets[m + 1];
    for (int j = s + threadIdx.x; j < e; j += 128) {
        const int c = cols[j];
        if (j > s && cols[j - 1] == c) continue;   // not head of duplicate run
        float sum = values[j];
        int jj = j + 1;
        while (jj < e && cols[jj] == c) { sum += values[jj]; jj++; }
        g_Wd[(size_t)m * K_DIM + c] = sum;
    }
}

__global__ void __launch_bounds__(256) convw_kernel() {
    size_t i = ((size_t)blockIdx.x * 256 + threadIdx.x) * 4;
    if (i >= (size_t)M_DIM * K_DIM) return;
    float4 w = *reinterpret_cast<const float4*>(&g_Wd[i]);
    __half h0 = __float2half_rn(w.x), h1 = __float2half_rn(w.y);
    __half h2 = __float2half_rn(w.z), h3 = __float2half_rn(w.w);
    __half l0 = __float2half_rn(w.x - __half2float(h0));
    __half l1 = __float2half_rn(w.y - __half2float(h1));
    __half l2 = __float2half_rn(w.z - __half2float(h2));
    __half l3 = __float2half_rn(w.w - __half2float(h3));
    *reinterpret_cast<__half2*>(&g_Whi[i])     = __halves2half2(h0, h1);
    *reinterpret_cast<__half2*>(&g_Whi[i + 2]) = __halves2half2(h2, h3);
    *reinterpret_cast<__half2*>(&g_Wlo[i])     = __halves2half2(l0, l1);
    *reinterpret_cast<__half2*>(&g_Wlo[i + 2]) = __halves2half2(l2, l3);
}

__global__ void __launch_bounds__(256) convx_kernel(const float* __restrict__ x) {
    size_t i = ((size_t)blockIdx.x * 256 + threadIdx.x) * 4;
    if (i >= (size_t)BN_DIM * K_DIM) return;
    float4 w = *reinterpret_cast<const float4*>(&x[i]);
    *reinterpret_cast<__half2*>(&g_Xh[i]) =
        __halves2half2(__float2half_rn(w.x), __float2half_rn(w.y));
    *reinterpret_cast<__half2*>(&g_Xh[i + 2]) =
        __halves2half2(__float2half_rn(w.z), __float2half_rn(w.w));
}

// ---------------- GEMM ------------------------------------------------------
// C[M, BN] = (Whi + Wlo) * Xh^T, fp32 accumulate, via mma.sync m16n8k16.
__global__ void __launch_bounds__(256, 1) gemm_kernel(float* __restrict__ out) {
    extern __shared__ char smem[];
    const int tid  = threadIdx.x;
    const int wid  = tid >> 5;
    const int lane = tid & 31;
    const int grp  = lane >> 2;     // 0..7
    const int tig  = lane & 3;      // 0..3
    const int wm0  = (wid & 3) * 32;
    const int wn0  = (wid >> 2) * 64;
    const int m0   = blockIdx.x * BM;
    const int bn0  = blockIdx.y * BN;

    const uint32_t sbase = smem_u32(smem);

    // per-thread cp.async assignment: 512 chunks (16 B) per operand tile,
    // chunk c: row = c>>2, kchunk = c&3. thread does c = tid, tid+256.
    // gmem: row-major [*, 4096] halves.
    const __half* gAhi = g_Whi + (size_t)m0  * K_DIM;
    const __half* gAlo = g_Wlo + (size_t)m0  * K_DIM;
    const __half* gB   = g_Xh  + (size_t)bn0 * K_DIM;

    #define LOAD_STAGE(stg, ktidx) do {                                        \
        const uint32_t sb_ = sbase + (stg) * STAGE_BYTES;                      \
        const int kh_ = (ktidx) * BK;                                          \
        _Pragma("unroll")                                                      \
        for (int i_ = 0; i_ < 2; i_++) {                                       \
            const int c_   = tid + i_ * 256;                                   \
            const int row_ = c_ >> 2, ch_ = c_ & 3;                            \
            const uint32_t d_ = sb_ + row_ * TILE_ROW_BYTES + ch_ * 16;        \
            const size_t  g_ = (size_t)row_ * K_DIM + kh_ + ch_ * 8;           \
            CP16(d_,                  gAhi + g_);                              \
            CP16(d_ + TILE_BYTES,     gAlo + g_);                              \
            CP16(d_ + 2 * TILE_BYTES, gB   + g_);                              \
        }                                                                      \
    } while (0)

    // prologue: stages 0..NSTAGE-2
    #pragma unroll
    for (int s = 0; s < NSTAGE - 1; s++) { LOAD_STAGE(s, s); CP_COMMIT(); }

    float acc[2][8][4];
    #pragma unroll
    for (int mt = 0; mt < 2; mt++)
        #pragma unroll
        for (int nt = 0; nt < 8; nt++)
            #pragma unroll
            for (int r = 0; r < 4; r++) acc[mt][nt][r] = 0.f;

    // fragment smem byte offsets (within a tile)
    // A row r, half-col c -> byte r*80 + c*2
    const int a_r0 = wm0 + grp;           // +16*mt, +8 for second row group
    const int b_r0 = wn0 + grp;           // +8*nt

    for (int kt = 0; kt < NKT; kt++) {
        CP_WAIT(NSTAGE - 2);
        __syncthreads();

        // prefetch next stage (overwrites stage computed last iteration; the
        // syncthreads above guarantees all warps are done reading it)
        if (kt + NSTAGE - 1 < NKT) LOAD_STAGE((kt + NSTAGE - 1) % NSTAGE, kt + NSTAGE - 1);
        CP_COMMIT();

        const char* st = smem + (kt % NSTAGE) * STAGE_BYTES;
        const char* sAhi = st;
        const char* sAlo = st + TILE_BYTES;
        const char* sB   = st + 2 * TILE_BYTES;

        #pragma unroll
        for (int ks = 0; ks < 2; ks++) {          // two k16 steps in BK=32
            const int kb = ks * 16 * 2 + tig * 4; // byte offset of 2*tig halves at k16 step
            // B fragments: 8 n-tiles x 2 regs
            uint32_t bf[8][2];
            #pragma unroll
            for (int nt = 0; nt < 8; nt++) {
                const char* p = sB + (b_r0 + 8 * nt) * TILE_ROW_BYTES + kb;
                bf[nt][0] = *reinterpret_cast<const uint32_t*>(p);
                bf[nt][1] = *reinterpret_cast<const uint32_t*>(p + 16);
            }
            #pragma unroll
            for (int mt = 0; mt < 2; mt++) {
                const int ar = (a_r0 + 16 * mt) * TILE_ROW_BYTES + kb;
                uint32_t ah[4], al[4];
                ah[0] = *reinterpret_cast<const uint32_t*>(sAhi + ar);
                ah[1] = *reinterpret_cast<const uint32_t*>(sAhi + ar + 8 * TILE_ROW_BYTES);
                ah[2] = *reinterpret_cast<const uint32_t*>(sAhi + ar + 16);
                ah[3] = *reinterpret_cast<const uint32_t*>(sAhi + ar + 8 * TILE_ROW_BYTES + 16);
                al[0] = *reinterpret_cast<const uint32_t*>(sAlo + ar);
                al[1] = *reinterpret_cast<const uint32_t*>(sAlo + ar + 8 * TILE_ROW_BYTES);
                al[2] = *reinterpret_cast<const uint32_t*>(sAlo + ar + 16);
                al[3] = *reinterpret_cast<const uint32_t*>(sAlo + ar + 8 * TILE_ROW_BYTES + 16);
                #pragma unroll
                for (int nt = 0; nt < 8; nt++) mma16816(acc[mt][nt], ah, bf[nt]);
                #pragma unroll
                for (int nt = 0; nt < 8; nt++) mma16816(acc[mt][nt], al, bf[nt]);
            }
        }
    }

    // epilogue: direct stores, fp32
    const int b  = bn0 / N_DIM;
    const int nb = bn0 % N_DIM;
    float* ob = out + (size_t)b * M_DIM * N_DIM;
    #pragma unroll
    for (int mt = 0; mt < 2; mt++) {
        const int row = m0 + wm0 + 16 * mt + grp;
        #pragma unroll
        for (int nt = 0; nt < 8; nt++) {
            const int col = nb + wn0 + 8 * nt + 2 * tig;
            float2 v0 = make_float2(acc[mt][nt][0], acc[mt][nt][1]);
            float2 v1 = make_float2(acc[mt][nt][2], acc[mt][nt][3]);
            *reinterpret_cast<float2*>(ob + (size_t)row * N_DIM + col)       = v0;
            *reinterpret_cast<float2*>(ob + (size_t)(row + 8) * N_DIM + col) = v1;
        }
    }
}

// ---------------- host side --------------------------------------------------
extern "C" void kernel_launch(void* const* d_in, const int* in_sizes, int n_in,
                              void* d_out, int out_size) {
    const float* x           = (const float*)d_in[0];  // [B, N, K] == [BN, K]
    const float* values      = (const float*)d_in[1];
    const int*   row_offsets = (const int*)  d_in[2];
    const int*   col_indices = (const int*)  d_in[3];
    float*       out         = (float*)d_out;
    (void)in_sizes; (void)n_in; (void)out_size;

    const size_t wN = (size_t)M_DIM * K_DIM;
    const size_t xN = (size_t)BN_DIM * K_DIM;

    zero_w_kernel<<<(unsigned)((wN / 4 + 255) / 256), 256>>>();
    scatter_kernel<<<M_DIM, 128>>>(values, row_offsets, col_indices);
    convw_kernel<<<(unsigned)((wN / 4 + 255) / 256), 256>>>();
    convx_kernel<<<(unsigned)((xN / 4 + 255) / 256), 256>>>(x);

    static bool attr_set = false;
    if (!attr_set) {
        cudaFuncSetAttribute(gemm_kernel,
                             cudaFuncAttributeMaxDynamicSharedMemorySize, SMEM_TOTAL);
        attr_set = true;
    }
    gemm_kernel<<<dim3(M_DIM / BM, BN_DIM / BN), 256, SMEM_TOTAL>>>(out);
}

// round 4
// speedup vs baseline: 2.7299x; 2.1335x over previous
#include <cuda_runtime.h>
#include <cuda_fp16.h>
#include <cstdint>

#define M_DIM 4096
#define K_DIM 4096
#define B_DIM 4
#define N_DIM 2048
#define BN_DIM (B_DIM * N_DIM)      // 8192

// GEMM tiling
#define BM 128
#define BN 256
#define BK 32                        // fp16 elems per k-tile
#define NSTAGE 4
#define PADK 40                      // pitch in halves (80 B): conflict-free ldmatrix
#define TRB (PADK * 2)               // tile row bytes = 80
#define A_TILE_BYTES (BM * TRB)      // 10240
#define B_TILE_BYTES (BN * TRB)      // 20480
#define STAGE_BYTES (A_TILE_BYTES + B_TILE_BYTES)   // 30720
#define SMEM_TOTAL (NSTAGE * STAGE_BYTES)           // 122880
#define NKT (K_DIM / BK)             // 128

// ---------------- scratch ----------------------------------------------------
__device__ __align__(1024) __half g_Wh[(size_t)M_DIM * K_DIM];
__device__ __align__(1024) __half g_Xh[(size_t)BN_DIM * K_DIM];

// ---------------- helpers ----------------------------------------------------
__device__ __forceinline__ uint32_t smem_u32(const void* p) {
    uint32_t a;
    asm("{ .reg .u64 t; cvta.to.shared.u64 t, %1; cvt.u32.u64 %0, t; }" : "=r"(a) : "l"(p));
    return a;
}

#define CP16(dst_u32, src_ptr) \
    asm volatile("cp.async.cg.shared.global [%0], [%1], 16;" \
                 :: "r"(dst_u32), "l"(src_ptr) : "memory")
#define CP_COMMIT() asm volatile("cp.async.commit_group;" ::: "memory")
#define CP_WAIT(n)  asm volatile("cp.async.wait_group %0;" :: "n"(n) : "memory")

__device__ __forceinline__ void ldsm_x4(uint32_t* r, uint32_t addr) {
    asm volatile("ldmatrix.sync.aligned.m8n8.x4.shared.b16 {%0,%1,%2,%3}, [%4];"
        : "=r"(r[0]), "=r"(r[1]), "=r"(r[2]), "=r"(r[3]) : "r"(addr));
}

__device__ __forceinline__ void mma16816(float* d, const uint32_t* a, const uint32_t* b) {
    asm volatile(
        "mma.sync.aligned.m16n8k16.row.col.f32.f16.f16.f32 "
        "{%0,%1,%2,%3}, {%4,%5,%6,%7}, {%8,%9}, {%0,%1,%2,%3};"
        : "+f"(d[0]), "+f"(d[1]), "+f"(d[2]), "+f"(d[3])
        : "r"(a[0]), "r"(a[1]), "r"(a[2]), "r"(a[3]), "r"(b[0]), "r"(b[1]));
}

// ---------------- prep kernels -----------------------------------------------
__global__ void __launch_bounds__(256) zero_wh_kernel() {
    size_t i = ((size_t)blockIdx.x * 256 + threadIdx.x) * 8;   // 8 halves = 16 B
    if (i < (size_t)M_DIM * K_DIM)
        *reinterpret_cast<float4*>(&g_Wh[i]) = make_float4(0.f, 0.f, 0.f, 0.f);
}

// Deterministic CSR scatter straight to fp16: fold duplicate runs in fp32.
__global__ void __launch_bounds__(128) scatter_kernel(
    const float* __restrict__ values, const int* __restrict__ row_offsets,
    const int* __restrict__ cols) {
    const int m = blockIdx.x;
    const int s = row_offsets[m], e = row_offsets[m + 1];
    for (int j = s + threadIdx.x; j < e; j += 128) {
        const int c = cols[j];
        if (j > s && cols[j - 1] == c) continue;
        float sum = values[j];
        int jj = j + 1;
        while (jj < e && cols[jj] == c) { sum += values[jj]; jj++; }
        g_Wh[(size_t)m * K_DIM + c] = __float2half_rn(sum);
    }
}

__global__ void __launch_bounds__(256) convx_kernel(const float* __restrict__ x) {
    size_t i = ((size_t)blockIdx.x * 256 + threadIdx.x) * 4;
    if (i >= (size_t)BN_DIM * K_DIM) return;
    float4 w = *reinterpret_cast<const float4*>(&x[i]);
    *reinterpret_cast<__half2*>(&g_Xh[i]) =
        __halves2half2(__float2half_rn(w.x), __float2half_rn(w.y));
    *reinterpret_cast<__half2*>(&g_Xh[i + 2]) =
        __halves2half2(__float2half_rn(w.z), __float2half_rn(w.w));
}

// ---------------- GEMM -------------------------------------------------------
// C[M, BN_DIM] = Wh * Xh^T, fp32 accumulate.  512 threads, warp grid 4x4,
// warp tile 32x64 (mt=2 m16 tiles, nt=8 n8 tiles).
__global__ void __launch_bounds__(512, 1) gemm_kernel(float* __restrict__ out) {
    extern __shared__ char smem[];
    const int tid  = threadIdx.x;
    const int wid  = tid >> 5;
    const int lane = tid & 31;
    const int grp  = lane >> 2;
    const int tig  = lane & 3;
    const int wm0  = (wid & 3) * 32;
    const int wn0  = (wid >> 2) * 64;
    const int m0   = blockIdx.x * BM;
    const int bn0  = blockIdx.y * BN;

    const uint32_t sbase = smem_u32(smem);

    // ldmatrix lane-derived address components
    const int a_row_l = (lane & 7) + 8 * ((lane >> 3) & 1);
    const int a_kx    = 16 * ((lane >> 4) & 1);
    const int b_row_l = (lane & 7) + 8 * ((lane >> 4) & 1);
    const int b_kx    = 16 * ((lane >> 3) & 1);

    const __half* gA = g_Wh + (size_t)m0  * K_DIM;
    const __half* gB = g_Xh + (size_t)bn0 * K_DIM;

    // cp.async: 1536 16-B chunks per stage (A:512, B:1024); 3 per thread.
    const int arow = tid >> 2, ach = tid & 3;   // A chunk tid, B chunks tid, tid+512
    #define LOAD_STAGE(stg, ktidx) do {                                         \
        const uint32_t sb_ = sbase + (stg) * STAGE_BYTES;                       \
        const int kh_ = (ktidx) * BK;                                           \
        const uint32_t d_  = sb_ + arow * TRB + ach * 16;                       \
        const size_t   g_  = (size_t)arow * K_DIM + kh_ + ach * 8;              \
        CP16(d_, gA + g_);                                                      \
        CP16(d_ + A_TILE_BYTES, gB + g_);                                       \
        CP16(d_ + A_TILE_BYTES + 128 * TRB, gB + g_ + (size_t)128 * K_DIM);     \
    } while (0)

    #pragma unroll
    for (int s = 0; s < NSTAGE - 1; s++) { LOAD_STAGE(s, s); CP_COMMIT(); }

    float acc[2][8][4];
    #pragma unroll
    for (int mt = 0; mt < 2; mt++)
        #pragma unroll
        for (int nt = 0; nt < 8; nt++)
            #pragma unroll
            for (int r = 0; r < 4; r++) acc[mt][nt][r] = 0.f;

    for (int kt = 0; kt < NKT; kt++) {
        CP_WAIT(NSTAGE - 2);
        __syncthreads();
        if (kt + NSTAGE - 1 < NKT) LOAD_STAGE((kt + NSTAGE - 1) % NSTAGE, kt + NSTAGE - 1);
        CP_COMMIT();

        const uint32_t st = sbase + (kt % NSTAGE) * STAGE_BYTES;
        const uint32_t sA = st;
        const uint32_t sB = st + A_TILE_BYTES;

        #pragma unroll
        for (int ks = 0; ks < 2; ks++) {
            const int kb = ks * 32;
            uint32_t bf[8][2];
            #pragma unroll
            for (int ntp = 0; ntp < 4; ntp++) {
                uint32_t r[4];
                ldsm_x4(r, sB + (wn0 + 16 * ntp + b_row_l) * TRB + kb + b_kx);
                bf[2 * ntp][0]     = r[0];
                bf[2 * ntp][1]     = r[1];
                bf[2 * ntp + 1][0] = r[2];
                bf[2 * ntp + 1][1] = r[3];
            }
            #pragma unroll
            for (int mt = 0; mt < 2; mt++) {
                uint32_t ah[4];
                ldsm_x4(ah, sA + (wm0 + 16 * mt + a_row_l) * TRB + kb + a_kx);
                #pragma unroll
                for (int nt = 0; nt < 8; nt++) mma16816(acc[mt][nt], ah, bf[nt]);
            }
        }
    }

    // epilogue
    const int b  = bn0 >> 11;               // / N_DIM
    const int nb = bn0 & (N_DIM - 1);
    float* ob = out + (size_t)b * M_DIM * N_DIM;
    #pragma unroll
    for (int mt = 0; mt < 2; mt++) {
        const int row = m0 + wm0 + 16 * mt + grp;
        #pragma unroll
        for (int nt = 0; nt < 8; nt++) {
            const int col = nb + wn0 + 8 * nt + 2 * tig;
            *reinterpret_cast<float2*>(ob + (size_t)row * N_DIM + col) =
                make_float2(acc[mt][nt][0], acc[mt][nt][1]);
            *reinterpret_cast<float2*>(ob + (size_t)(row + 8) * N_DIM + col) =
                make_float2(acc[mt][nt][2], acc[mt][nt][3]);
        }
    }
}

// ---------------- host side --------------------------------------------------
extern "C" void kernel_launch(void* const* d_in, const int* in_sizes, int n_in,
                              void* d_out, int out_size) {
    const float* x           = (const float*)d_in[0];  // [B, N, K] == [BN, K]
    const float* values      = (const float*)d_in[1];
    const int*   row_offsets = (const int*)  d_in[2];
    const int*   col_indices = (const int*)  d_in[3];
    float*       out         = (float*)d_out;
    (void)in_sizes; (void)n_in; (void)out_size;

    const size_t wN = (size_t)M_DIM * K_DIM;
    const size_t xN = (size_t)BN_DIM * K_DIM;

    zero_wh_kernel<<<(unsigned)((wN / 8 + 255) / 256), 256>>>();
    scatter_kernel<<<M_DIM, 128>>>(values, row_offsets, col_indices);
    convx_kernel<<<(unsigned)((xN / 4 + 255) / 256), 256>>>(x);

    cudaFuncSetAttribute(gemm_kernel,
                         cudaFuncAttributeMaxDynamicSharedMemorySize, SMEM_TOTAL);
    gemm_kernel<<<dim3(M_DIM / BM, BN_DIM / BN), 512, SMEM_TOTAL>>>(out);
}

// round 5
// speedup vs baseline: 2.9648x; 1.0861x over previous
#include <cuda_runtime.h>
#include <cuda_fp16.h>
#include <cstdint>

#define M_DIM 4096
#define K_DIM 4096
#define B_DIM 4
#define N_DIM 2048
#define BN_DIM (B_DIM * N_DIM)      // 8192

// GEMM tiling
#define BM 128
#define BN 128
#define BK 32                        // fp16 elems per k-tile
#define NSTAGE 4
#define PADK 40                      // pitch in halves (80 B): conflict-free ldmatrix
#define TRB (PADK * 2)               // tile row bytes = 80
#define A_TILE_BYTES (BM * TRB)      // 10240
#define B_TILE_BYTES (BN * TRB)      // 10240
#define STAGE_BYTES (A_TILE_BYTES + B_TILE_BYTES)   // 20480
#define SMEM_TOTAL (NSTAGE * STAGE_BYTES)           // 81920 -> 2 CTAs/SM
#define NKT (K_DIM / BK)             // 128

// ---------------- scratch ----------------------------------------------------
__device__ __align__(1024) __half g_Wh[(size_t)M_DIM * K_DIM];
__device__ __align__(1024) __half g_Xh[(size_t)BN_DIM * K_DIM];

// ---------------- helpers ----------------------------------------------------
__device__ __forceinline__ uint32_t smem_u32(const void* p) {
    uint32_t a;
    asm("{ .reg .u64 t; cvta.to.shared.u64 t, %1; cvt.u32.u64 %0, t; }" : "=r"(a) : "l"(p));
    return a;
}

#define CP16(dst_u32, src_ptr) \
    asm volatile("cp.async.cg.shared.global [%0], [%1], 16;" \
                 :: "r"(dst_u32), "l"(src_ptr) : "memory")
#define CP_COMMIT() asm volatile("cp.async.commit_group;" ::: "memory")
#define CP_WAIT(n)  asm volatile("cp.async.wait_group %0;" :: "n"(n) : "memory")

__device__ __forceinline__ void ldsm_x4(uint32_t* r, uint32_t addr) {
    asm volatile("ldmatrix.sync.aligned.m8n8.x4.shared.b16 {%0,%1,%2,%3}, [%4];"
        : "=r"(r[0]), "=r"(r[1]), "=r"(r[2]), "=r"(r[3]) : "r"(addr));
}

__device__ __forceinline__ void mma16816(float* d, const uint32_t* a, const uint32_t* b) {
    asm volatile(
        "mma.sync.aligned.m16n8k16.row.col.f32.f16.f16.f32 "
        "{%0,%1,%2,%3}, {%4,%5,%6,%7}, {%8,%9}, {%0,%1,%2,%3};"
        : "+f"(d[0]), "+f"(d[1]), "+f"(d[2]), "+f"(d[3])
        : "r"(a[0]), "r"(a[1]), "r"(a[2]), "r"(a[3]), "r"(b[0]), "r"(b[1]));
}

// ---------------- prep kernels -----------------------------------------------
__global__ void __launch_bounds__(256) zero_wh_kernel() {
    size_t i = ((size_t)blockIdx.x * 256 + threadIdx.x) * 8;   // 8 halves = 16 B
    if (i < (size_t)M_DIM * K_DIM)
        *reinterpret_cast<float4*>(&g_Wh[i]) = make_float4(0.f, 0.f, 0.f, 0.f);
}

// Deterministic CSR scatter straight to fp16: fold duplicate runs in fp32.
__global__ void __launch_bounds__(128) scatter_kernel(
    const float* __restrict__ values, const int* __restrict__ row_offsets,
    const int* __restrict__ cols) {
    const int m = blockIdx.x;
    const int s = row_offsets[m], e = row_offsets[m + 1];
    for (int j = s + threadIdx.x; j < e; j += 128) {
        const int c = cols[j];
        if (j > s && cols[j - 1] == c) continue;
        float sum = values[j];
        int jj = j + 1;
        while (jj < e && cols[jj] == c) { sum += values[jj]; jj++; }
        g_Wh[(size_t)m * K_DIM + c] = __float2half_rn(sum);
    }
}

__global__ void __launch_bounds__(256) convx_kernel(const float* __restrict__ x) {
    size_t i = ((size_t)blockIdx.x * 256 + threadIdx.x) * 4;
    if (i >= (size_t)BN_DIM * K_DIM) return;
    float4 w = *reinterpret_cast<const float4*>(&x[i]);
    *reinterpret_cast<__half2*>(&g_Xh[i]) =
        __halves2half2(__float2half_rn(w.x), __float2half_rn(w.y));
    *reinterpret_cast<__half2*>(&g_Xh[i + 2]) =
        __halves2half2(__float2half_rn(w.z), __float2half_rn(w.w));
}

// ---------------- GEMM -------------------------------------------------------
// C[M, BN_DIM] = Wh * Xh^T, fp32 accumulate.  256 threads, warp grid 4x2,
// warp tile 32x64 (mt=2 m16 tiles, nt=8 n8 tiles).  2 CTAs/SM.
__global__ void __launch_bounds__(256, 2) gemm_kernel(float* __restrict__ out) {
    extern __shared__ char smem[];
    const int tid  = threadIdx.x;
    const int wid  = tid >> 5;
    const int lane = tid & 31;
    const int grp  = lane >> 2;
    const int tig  = lane & 3;
    const int wm0  = (wid & 3) * 32;
    const int wn0  = (wid >> 2) * 64;
    const int m0   = blockIdx.x * BM;
    const int bn0  = blockIdx.y * BN;

    const uint32_t sbase = smem_u32(smem);

    // ldmatrix lane-derived address components
    const int a_row_l = (lane & 7) + 8 * ((lane >> 3) & 1);
    const int a_kx    = 16 * ((lane >> 4) & 1);
    const int b_row_l = (lane & 7) + 8 * ((lane >> 4) & 1);
    const int b_kx    = 16 * ((lane >> 3) & 1);

    const __half* gA = g_Wh + (size_t)m0  * K_DIM;
    const __half* gB = g_Xh + (size_t)bn0 * K_DIM;

    // cp.async per stage: A 512 chunks + B 512 chunks (16 B each), 256 threads
    // -> each thread: 2 A chunks + 2 B chunks.
    #define LOAD_STAGE(stg, ktidx) do {                                         \
        const uint32_t sb_ = sbase + (stg) * STAGE_BYTES;                       \
        const int kh_ = (ktidx) * BK;                                           \
        _Pragma("unroll")                                                       \
        for (int i_ = 0; i_ < 2; i_++) {                                        \
            const int c_   = tid + i_ * 256;                                    \
            const int row_ = c_ >> 2, ch_ = c_ & 3;                             \
            const uint32_t d_ = sb_ + row_ * TRB + ch_ * 16;                    \
            const size_t  g_  = (size_t)row_ * K_DIM + kh_ + ch_ * 8;           \
            CP16(d_, gA + g_);                                                  \
            CP16(d_ + A_TILE_BYTES, gB + g_);                                   \
        }                                                                       \
    } while (0)

    #pragma unroll
    for (int s = 0; s < NSTAGE - 1; s++) { LOAD_STAGE(s, s); CP_COMMIT(); }

    float acc[2][8][4];
    #pragma unroll
    for (int mt = 0; mt < 2; mt++)
        #pragma unroll
        for (int nt = 0; nt < 8; nt++)
            #pragma unroll
            for (int r = 0; r < 4; r++) acc[mt][nt][r] = 0.f;

    for (int kt = 0; kt < NKT; kt++) {
        CP_WAIT(NSTAGE - 2);
        __syncthreads();
        if (kt + NSTAGE - 1 < NKT) LOAD_STAGE((kt + NSTAGE - 1) % NSTAGE, kt + NSTAGE - 1);
        CP_COMMIT();

        const uint32_t st = sbase + (kt % NSTAGE) * STAGE_BYTES;
        const uint32_t sA = st;
        const uint32_t sB = st + A_TILE_BYTES;

        #pragma unroll
        for (int ks = 0; ks < 2; ks++) {
            const int kb = ks * 32;
            uint32_t bf[8][2];
            #pragma unroll
            for (int ntp = 0; ntp < 4; ntp++) {
                uint32_t r[4];
                ldsm_x4(r, sB + (wn0 + 16 * ntp + b_row_l) * TRB + kb + b_kx);
                bf[2 * ntp][0]     = r[0];
                bf[2 * ntp][1]     = r[1];
                bf[2 * ntp + 1][0] = r[2];
                bf[2 * ntp + 1][1] = r[3];
            }
            #pragma unroll
            for (int mt = 0; mt < 2; mt++) {
                uint32_t ah[4];
                ldsm_x4(ah, sA + (wm0 + 16 * mt + a_row_l) * TRB + kb + a_kx);
                #pragma unroll
                for (int nt = 0; nt < 8; nt++) mma16816(acc[mt][nt], ah, bf[nt]);
            }
        }
    }

    // epilogue
    const int b  = bn0 >> 11;               // / N_DIM
    const int nb = bn0 & (N_DIM - 1);
    float* ob = out + (size_t)b * M_DIM * N_DIM;
    #pragma unroll
    for (int mt = 0; mt < 2; mt++) {
        const int row = m0 + wm0 + 16 * mt + grp;
        #pragma unroll
        for (int nt = 0; nt < 8; nt++) {
            const int col = nb + wn0 + 8 * nt + 2 * tig;
            *reinterpret_cast<float2*>(ob + (size_t)row * N_DIM + col) =
                make_float2(acc[mt][nt][0], acc[mt][nt][1]);
            *reinterpret_cast<float2*>(ob + (size_t)(row + 8) * N_DIM + col) =
                make_float2(acc[mt][nt][2], acc[mt][nt][3]);
        }
    }
}

// ---------------- host side --------------------------------------------------
extern "C" void kernel_launch(void* const* d_in, const int* in_sizes, int n_in,
                              void* d_out, int out_size) {
    const float* x           = (const float*)d_in[0];  // [B, N, K] == [BN, K]
    const float* values      = (const float*)d_in[1];
    const int*   row_offsets = (const int*)  d_in[2];
    const int*   col_indices = (const int*)  d_in[3];
    float*       out         = (float*)d_out;
    (void)in_sizes; (void)n_in; (void)out_size;

    const size_t wN = (size_t)M_DIM * K_DIM;
    const size_t xN = (size_t)BN_DIM * K_DIM;

    zero_wh_kernel<<<(unsigned)((wN / 8 + 255) / 256), 256>>>();
    scatter_kernel<<<M_DIM, 128>>>(values, row_offsets, col_indices);
    convx_kernel<<<(unsigned)((xN / 4 + 255) / 256), 256>>>(x);

    cudaFuncSetAttribute(gemm_kernel,
                         cudaFuncAttributeMaxDynamicSharedMemorySize, SMEM_TOTAL);
    gemm_kernel<<<dim3(M_DIM / BM, BN_DIM / BN), 256, SMEM_TOTAL>>>(out);
}

// round 6
// speedup vs baseline: 2.9949x; 1.0102x over previous
#include <cuda_runtime.h>
#include <cuda_fp16.h>
#include <cstdint>

#define M_DIM 4096
#define K_DIM 4096
#define B_DIM 4
#define N_DIM 2048
#define BN_DIM (B_DIM * N_DIM)      // 8192

// GEMM tiling
#define BM 128
#define BN 128
#define BK 64                        // fp16 elems per k-tile (4 k16 steps)
#define NSTAGE 3
#define PADK 72                      // pitch in halves (144 B): conflict-free ldmatrix
#define TRB (PADK * 2)               // tile row bytes = 144
#define A_TILE_BYTES (BM * TRB)      // 18432
#define B_TILE_BYTES (BN * TRB)      // 18432
#define STAGE_BYTES (A_TILE_BYTES + B_TILE_BYTES)   // 36864
#define SMEM_TOTAL (NSTAGE * STAGE_BYTES)           // 110592 -> 2 CTAs/SM
#define NKT (K_DIM / BK)             // 64

// ---------------- scratch ----------------------------------------------------
__device__ __align__(1024) __half g_Wh[(size_t)M_DIM * K_DIM];
__device__ __align__(1024) __half g_Xh[(size_t)BN_DIM * K_DIM];

// ---------------- helpers ----------------------------------------------------
__device__ __forceinline__ uint32_t smem_u32(const void* p) {
    uint32_t a;
    asm("{ .reg .u64 t; cvta.to.shared.u64 t, %1; cvt.u32.u64 %0, t; }" : "=r"(a) : "l"(p));
    return a;
}

#define CP16(dst_u32, src_ptr) \
    asm volatile("cp.async.cg.shared.global [%0], [%1], 16;" \
                 :: "r"(dst_u32), "l"(src_ptr) : "memory")
#define CP_COMMIT() asm volatile("cp.async.commit_group;" ::: "memory")
#define CP_WAIT(n)  asm volatile("cp.async.wait_group %0;" :: "n"(n) : "memory")

__device__ __forceinline__ void ldsm_x4(uint32_t* r, uint32_t addr) {
    asm volatile("ldmatrix.sync.aligned.m8n8.x4.shared.b16 {%0,%1,%2,%3}, [%4];"
        : "=r"(r[0]), "=r"(r[1]), "=r"(r[2]), "=r"(r[3]) : "r"(addr));
}

__device__ __forceinline__ void mma16816(float* d, const uint32_t* a, const uint32_t* b) {
    asm volatile(
        "mma.sync.aligned.m16n8k16.row.col.f32.f16.f16.f32 "
        "{%0,%1,%2,%3}, {%4,%5,%6,%7}, {%8,%9}, {%0,%1,%2,%3};"
        : "+f"(d[0]), "+f"(d[1]), "+f"(d[2]), "+f"(d[3])
        : "r"(a[0]), "r"(a[1]), "r"(a[2]), "r"(a[3]), "r"(b[0]), "r"(b[1]));
}

// ---------------- prep kernels -----------------------------------------------
__global__ void __launch_bounds__(256) zero_wh_kernel() {
    size_t i = ((size_t)blockIdx.x * 256 + threadIdx.x) * 8;   // 8 halves = 16 B
    if (i < (size_t)M_DIM * K_DIM)
        *reinterpret_cast<float4*>(&g_Wh[i]) = make_float4(0.f, 0.f, 0.f, 0.f);
}

// Deterministic CSR scatter straight to fp16: fold duplicate runs in fp32.
__global__ void __launch_bounds__(128) scatter_kernel(
    const float* __restrict__ values, const int* __restrict__ row_offsets,
    const int* __restrict__ cols) {
    const int m = blockIdx.x;
    const int s = row_offsets[m], e = row_offsets[m + 1];
    for (int j = s + threadIdx.x; j < e; j += 128) {
        const int c = cols[j];
        if (j > s && cols[j - 1] == c) continue;
        float sum = values[j];
        int jj = j + 1;
        while (jj < e && cols[jj] == c) { sum += values[jj]; jj++; }
        g_Wh[(size_t)m * K_DIM + c] = __float2half_rn(sum);
    }
}

__global__ void __launch_bounds__(256) convx_kernel(const float* __restrict__ x) {
    size_t i = ((size_t)blockIdx.x * 256 + threadIdx.x) * 4;
    if (i >= (size_t)BN_DIM * K_DIM) return;
    float4 w = *reinterpret_cast<const float4*>(&x[i]);
    *reinterpret_cast<__half2*>(&g_Xh[i]) =
        __halves2half2(__float2half_rn(w.x), __float2half_rn(w.y));
    *reinterpret_cast<__half2*>(&g_Xh[i + 2]) =
        __halves2half2(__float2half_rn(w.z), __float2half_rn(w.w));
}

// ---------------- GEMM -------------------------------------------------------
// C[M, BN_DIM] = Wh * Xh^T, fp32 accumulate.  256 threads, warp grid 4x2,
// warp tile 32x64.  2 CTAs/SM.  Register-double-buffered fragments.
__global__ void __launch_bounds__(256, 2) gemm_kernel(float* __restrict__ out) {
    extern __shared__ char smem[];
    const int tid  = threadIdx.x;
    const int wid  = tid >> 5;
    const int lane = tid & 31;
    const int grp  = lane >> 2;
    const int tig  = lane & 3;
    const int wm0  = (wid & 3) * 32;
    const int wn0  = (wid >> 2) * 64;
    const int m0   = blockIdx.x * BM;
    const int bn0  = blockIdx.y * BN;

    const uint32_t sbase = smem_u32(smem);

    // ldmatrix lane-derived address components
    const int a_row_l = (lane & 7) + 8 * ((lane >> 3) & 1);
    const int a_kx    = 16 * ((lane >> 4) & 1);
    const int b_row_l = (lane & 7) + 8 * ((lane >> 4) & 1);
    const int b_kx    = 16 * ((lane >> 3) & 1);

    const __half* gA = g_Wh + (size_t)m0  * K_DIM;
    const __half* gB = g_Xh + (size_t)bn0 * K_DIM;

    // cp.async per stage: 1024 chunks A + 1024 chunks B (16 B each), 256 thr
    // -> 4 A + 4 B chunks per thread.  chunk c: row = c>>3, ch = c&7.
    #define LOAD_STAGE(stg, ktidx) do {                                         \
        const uint32_t sb_ = sbase + (stg) * STAGE_BYTES;                       \
        const int kh_ = (ktidx) * BK;                                           \
        _Pragma("unroll")                                                       \
        for (int i_ = 0; i_ < 4; i_++) {                                        \
            const int c_   = tid + i_ * 256;                                    \
            const int row_ = c_ >> 3, ch_ = c_ & 7;                             \
            const uint32_t d_ = sb_ + row_ * TRB + ch_ * 16;                    \
            const size_t  g_  = (size_t)row_ * K_DIM + kh_ + ch_ * 8;           \
            CP16(d_, gA + g_);                                                  \
            CP16(d_ + A_TILE_BYTES, gB + g_);                                   \
        }                                                                       \
    } while (0)

    #pragma unroll
    for (int s = 0; s < NSTAGE - 1; s++) { LOAD_STAGE(s, s); CP_COMMIT(); }

    float acc[2][8][4];
    #pragma unroll
    for (int mt = 0; mt < 2; mt++)
        #pragma unroll
        for (int nt = 0; nt < 8; nt++)
            #pragma unroll
            for (int r = 0; r < 4; r++) acc[mt][nt][r] = 0.f;

    uint32_t bfb[2][8][2];   // B fragments, double-buffered
    uint32_t ahb[2][2][4];   // A fragments, double-buffered

    #define LOAD_FRAGS(sA_, sB_, ks_, buf_) do {                                \
        const int kb_ = (ks_) * 32;                                             \
        _Pragma("unroll")                                                       \
        for (int ntp = 0; ntp < 4; ntp++) {                                     \
            uint32_t r_[4];                                                     \
            ldsm_x4(r_, (sB_) + (wn0 + 16 * ntp + b_row_l) * TRB + kb_ + b_kx); \
            bfb[buf_][2 * ntp][0]     = r_[0];                                  \
            bfb[buf_][2 * ntp][1]     = r_[1];                                  \
            bfb[buf_][2 * ntp + 1][0] = r_[2];                                  \
            bfb[buf_][2 * ntp + 1][1] = r_[3];                                  \
        }                                                                       \
        _Pragma("unroll")                                                       \
        for (int mt = 0; mt < 2; mt++)                                          \
            ldsm_x4(ahb[buf_][mt],                                              \
                    (sA_) + (wm0 + 16 * mt + a_row_l) * TRB + kb_ + a_kx);      \
    } while (0)

    for (int kt = 0; kt < NKT; kt++) {
        CP_WAIT(NSTAGE - 2);
        __syncthreads();
        if (kt + NSTAGE - 1 < NKT) LOAD_STAGE((kt + NSTAGE - 1) % NSTAGE, kt + NSTAGE - 1);
        CP_COMMIT();

        const uint32_t st = sbase + (kt % NSTAGE) * STAGE_BYTES;
        const uint32_t sA = st;
        const uint32_t sB = st + A_TILE_BYTES;

        LOAD_FRAGS(sA, sB, 0, 0);

        #pragma unroll
        for (int ks = 0; ks < 4; ks++) {
            const int cur = ks & 1;
            if (ks < 3) LOAD_FRAGS(sA, sB, ks + 1, cur ^ 1);
            #pragma unroll
            for (int mt = 0; mt < 2; mt++)
                #pragma unroll
                for (int nt = 0; nt < 8; nt++)
                    mma16816(acc[mt][nt], ahb[cur][mt], bfb[cur][nt]);
        }
    }

    // epilogue
    const int b  = bn0 >> 11;               // / N_DIM
    const int nb = bn0 & (N_DIM - 1);
    float* ob = out + (size_t)b * M_DIM * N_DIM;
    #pragma unroll
    for (int mt = 0; mt < 2; mt++) {
        const int row = m0 + wm0 + 16 * mt + grp;
        #pragma unroll
        for (int nt = 0; nt < 8; nt++) {
            const int col = nb + wn0 + 8 * nt + 2 * tig;
            *reinterpret_cast<float2*>(ob + (size_t)row * N_DIM + col) =
                make_float2(acc[mt][nt][0], acc[mt][nt][1]);
            *reinterpret_cast<float2*>(ob + (size_t)(row + 8) * N_DIM + col) =
                make_float2(acc[mt][nt][2], acc[mt][nt][3]);
        }
    }
}

// ---------------- host side --------------------------------------------------
extern "C" void kernel_launch(void* const* d_in, const int* in_sizes, int n_in,
                              void* d_out, int out_size) {
    const float* x           = (const float*)d_in[0];  // [B, N, K] == [BN, K]
    const float* values      = (const float*)d_in[1];
    const int*   row_offsets = (const int*)  d_in[2];
    const int*   col_indices = (const int*)  d_in[3];
    float*       out         = (float*)d_out;
    (void)in_sizes; (void)n_in; (void)out_size;

    const size_t wN = (size_t)M_DIM * K_DIM;
    const size_t xN = (size_t)BN_DIM * K_DIM;

    zero_wh_kernel<<<(unsigned)((wN / 8 + 255) / 256), 256>>>();
    scatter_kernel<<<M_DIM, 128>>>(values, row_offsets, col_indices);
    convx_kernel<<<(unsigned)((xN / 4 + 255) / 256), 256>>>(x);

    cudaFuncSetAttribute(gemm_kernel,
                         cudaFuncAttributeMaxDynamicSharedMemorySize, SMEM_TOTAL);
    gemm_kernel<<<dim3(M_DIM / BM, BN_DIM / BN), 256, SMEM_TOTAL>>>(out);
}

// round 7
// speedup vs baseline: 3.0200x; 1.0084x over previous
#include <cuda_runtime.h>
#include <cuda_fp16.h>
#include <cstdint>

#define M_DIM 4096
#define K_DIM 4096
#define B_DIM 4
#define N_DIM 2048
#define BN_DIM (B_DIM * N_DIM)      // 8192

// GEMM tiling: CTA 128x128, 4 warps of 64x64, BK=64
#define BM 128
#define BN 128
#define BK 64                        // fp16 elems per k-tile (4 k16 steps)
#define NSTAGE 3
#define PADK 72                      // pitch in halves (144 B): conflict-free ldmatrix
#define TRB (PADK * 2)               // tile row bytes = 144
#define A_TILE_BYTES (BM * TRB)      // 18432
#define B_TILE_BYTES (BN * TRB)      // 18432
#define STAGE_BYTES (A_TILE_BYTES + B_TILE_BYTES)   // 36864
#define SMEM_TOTAL (NSTAGE * STAGE_BYTES)           // 110592 -> 2 CTAs/SM
#define NKT (K_DIM / BK)             // 64

// ---------------- scratch ----------------------------------------------------
__device__ __align__(1024) __half g_Wh[(size_t)M_DIM * K_DIM];
__device__ __align__(1024) __half g_Xh[(size_t)BN_DIM * K_DIM];

// ---------------- helpers ----------------------------------------------------
__device__ __forceinline__ uint32_t smem_u32(const void* p) {
    uint32_t a;
    asm("{ .reg .u64 t; cvta.to.shared.u64 t, %1; cvt.u32.u64 %0, t; }" : "=r"(a) : "l"(p));
    return a;
}

#define CP16(dst_u32, src_ptr) \
    asm volatile("cp.async.cg.shared.global [%0], [%1], 16;" \
                 :: "r"(dst_u32), "l"(src_ptr) : "memory")
#define CP_COMMIT() asm volatile("cp.async.commit_group;" ::: "memory")
#define CP_WAIT(n)  asm volatile("cp.async.wait_group %0;" :: "n"(n) : "memory")

__device__ __forceinline__ void ldsm_x4(uint32_t* r, uint32_t addr) {
    asm volatile("ldmatrix.sync.aligned.m8n8.x4.shared.b16 {%0,%1,%2,%3}, [%4];"
        : "=r"(r[0]), "=r"(r[1]), "=r"(r[2]), "=r"(r[3]) : "r"(addr));
}

__device__ __forceinline__ void mma16816(float* d, const uint32_t* a, const uint32_t* b) {
    asm volatile(
        "mma.sync.aligned.m16n8k16.row.col.f32.f16.f16.f32 "
        "{%0,%1,%2,%3}, {%4,%5,%6,%7}, {%8,%9}, {%0,%1,%2,%3};"
        : "+f"(d[0]), "+f"(d[1]), "+f"(d[2]), "+f"(d[3])
        : "r"(a[0]), "r"(a[1]), "r"(a[2]), "r"(a[3]), "r"(b[0]), "r"(b[1]));
}

// ---------------- prep kernels -----------------------------------------------
__global__ void __launch_bounds__(256) zero_wh_kernel() {
    size_t i = ((size_t)blockIdx.x * 256 + threadIdx.x) * 8;   // 8 halves = 16 B
    if (i < (size_t)M_DIM * K_DIM)
        *reinterpret_cast<float4*>(&g_Wh[i]) = make_float4(0.f, 0.f, 0.f, 0.f);
}

// Deterministic CSR scatter straight to fp16: fold duplicate runs in fp32.
__global__ void __launch_bounds__(128) scatter_kernel(
    const float* __restrict__ values, const int* __restrict__ row_offsets,
    const int* __restrict__ cols) {
    const int m = blockIdx.x;
    const int s = row_offsets[m], e = row_offsets[m + 1];
    for (int j = s + threadIdx.x; j < e; j += 128) {
        const int c = cols[j];
        if (j > s && cols[j - 1] == c) continue;
        float sum = values[j];
        int jj = j + 1;
        while (jj < e && cols[jj] == c) { sum += values[jj]; jj++; }
        g_Wh[(size_t)m * K_DIM + c] = __float2half_rn(sum);
    }
}

__global__ void __launch_bounds__(256) convx_kernel(const float* __restrict__ x) {
    size_t i = ((size_t)blockIdx.x * 256 + threadIdx.x) * 4;
    if (i >= (size_t)BN_DIM * K_DIM) return;
    float4 w = *reinterpret_cast<const float4*>(&x[i]);
    *reinterpret_cast<__half2*>(&g_Xh[i]) =
        __halves2half2(__float2half_rn(w.x), __float2half_rn(w.y));
    *reinterpret_cast<__half2*>(&g_Xh[i + 2]) =
        __halves2half2(__float2half_rn(w.z), __float2half_rn(w.w));
}

// ---------------- GEMM -------------------------------------------------------
// C[M, BN_DIM] = Wh * Xh^T, fp32 accumulate.  128 threads, warp grid 2x2,
// warp tile 64x64 (mt=4 m16 tiles, nt=8 n8 tiles).  2 CTAs/SM.
__global__ void __launch_bounds__(128, 2) gemm_kernel(float* __restrict__ out) {
    extern __shared__ char smem[];
    const int tid  = threadIdx.x;
    const int wid  = tid >> 5;
    const int lane = tid & 31;
    const int grp  = lane >> 2;
    const int tig  = lane & 3;
    const int wm0  = (wid & 1) * 64;
    const int wn0  = (wid >> 1) * 64;
    const int m0   = blockIdx.x * BM;
    const int bn0  = blockIdx.y * BN;

    const uint32_t sbase = smem_u32(smem);

    // ldmatrix lane-derived address components
    const int a_row_l = (lane & 7) + 8 * ((lane >> 3) & 1);
    const int a_kx    = 16 * ((lane >> 4) & 1);
    const int b_row_l = (lane & 7) + 8 * ((lane >> 4) & 1);
    const int b_kx    = 16 * ((lane >> 3) & 1);

    const __half* gA = g_Wh + (size_t)m0  * K_DIM;
    const __half* gB = g_Xh + (size_t)bn0 * K_DIM;

    // cp.async per stage: 1024 chunks A + 1024 chunks B (16 B each), 128 thr
    // -> 8 A + 8 B chunks per thread.  chunk c: row = c>>3, ch = c&7.
    #define LOAD_STAGE(stg, ktidx) do {                                         \
        const uint32_t sb_ = sbase + (stg) * STAGE_BYTES;                       \
        const int kh_ = (ktidx) * BK;                                           \
        _Pragma("unroll")                                                       \
        for (int i_ = 0; i_ < 8; i_++) {                                        \
            const int c_   = tid + i_ * 128;                                    \
            const int row_ = c_ >> 3, ch_ = c_ & 7;                             \
            const uint32_t d_ = sb_ + row_ * TRB + ch_ * 16;                    \
            const size_t  g_  = (size_t)row_ * K_DIM + kh_ + ch_ * 8;           \
            CP16(d_, gA + g_);                                                  \
            CP16(d_ + A_TILE_BYTES, gB + g_);                                   \
        }                                                                       \
    } while (0)

    #pragma unroll
    for (int s = 0; s < NSTAGE - 1; s++) { LOAD_STAGE(s, s); CP_COMMIT(); }

    float acc[4][8][4];
    #pragma unroll
    for (int mt = 0; mt < 4; mt++)
        #pragma unroll
        for (int nt = 0; nt < 8; nt++)
            #pragma unroll
            for (int r = 0; r < 4; r++) acc[mt][nt][r] = 0.f;

    for (int kt = 0; kt < NKT; kt++) {
        CP_WAIT(NSTAGE - 2);
        __syncthreads();
        if (kt + NSTAGE - 1 < NKT) LOAD_STAGE((kt + NSTAGE - 1) % NSTAGE, kt + NSTAGE - 1);
        CP_COMMIT();

        const uint32_t st = sbase + (kt % NSTAGE) * STAGE_BYTES;
        const uint32_t sA = st;
        const uint32_t sB = st + A_TILE_BYTES;

        #pragma unroll
        for (int ks = 0; ks < 4; ks++) {
            const int kb = ks * 32;
            uint32_t bf[8][2];
            #pragma unroll
            for (int ntp = 0; ntp < 4; ntp++) {
                uint32_t r[4];
                ldsm_x4(r, sB + (wn0 + 16 * ntp + b_row_l) * TRB + kb + b_kx);
                bf[2 * ntp][0]     = r[0];
                bf[2 * ntp][1]     = r[1];
                bf[2 * ntp + 1][0] = r[2];
                bf[2 * ntp + 1][1] = r[3];
            }
            uint32_t ah[4][4];
            #pragma unroll
            for (int mt = 0; mt < 4; mt++)
                ldsm_x4(ah[mt], sA + (wm0 + 16 * mt + a_row_l) * TRB + kb + a_kx);
            #pragma unroll
            for (int mt = 0; mt < 4; mt++)
                #pragma unroll
                for (int nt = 0; nt < 8; nt++)
                    mma16816(acc[mt][nt], ah[mt], bf[nt]);
        }
    }

    // epilogue
    const int b  = bn0 >> 11;               // / N_DIM
    const int nb = bn0 & (N_DIM - 1);
    float* ob = out + (size_t)b * M_DIM * N_DIM;
    #pragma unroll
    for (int mt = 0; mt < 4; mt++) {
        const int row = m0 + wm0 + 16 * mt + grp;
        #pragma unroll
        for (int nt = 0; nt < 8; nt++) {
            const int col = nb + wn0 + 8 * nt + 2 * tig;
            *reinterpret_cast<float2*>(ob + (size_t)row * N_DIM + col) =
                make_float2(acc[mt][nt][0], acc[mt][nt][1]);
            *reinterpret_cast<float2*>(ob + (size_t)(row + 8) * N_DIM + col) =
                make_float2(acc[mt][nt][2], acc[mt][nt][3]);
        }
    }
}

// ---------------- host side --------------------------------------------------
extern "C" void kernel_launch(void* const* d_in, const int* in_sizes, int n_in,
                              void* d_out, int out_size) {
    const float* x           = (const float*)d_in[0];  // [B, N, K] == [BN, K]
    const float* values      = (const float*)d_in[1];
    const int*   row_offsets = (const int*)  d_in[2];
    const int*   col_indices = (const int*)  d_in[3];
    float*       out         = (float*)d_out;
    (void)in_sizes; (void)n_in; (void)out_size;

    const size_t wN = (size_t)M_DIM * K_DIM;
    const size_t xN = (size_t)BN_DIM * K_DIM;

    zero_wh_kernel<<<(unsigned)((wN / 8 + 255) / 256), 256>>>();
    scatter_kernel<<<M_DIM, 128>>>(values, row_offsets, col_indices);
    convx_kernel<<<(unsigned)((xN / 4 + 255) / 256), 256>>>(x);

    cudaFuncSetAttribute(gemm_kernel,
                         cudaFuncAttributeMaxDynamicSharedMemorySize, SMEM_TOTAL);
    gemm_kernel<<<dim3(M_DIM / BM, BN_DIM / BN), 128, SMEM_TOTAL>>>(out);
}